// round 1
// baseline (speedup 1.0000x reference)
#include <cuda_runtime.h>
#include <math.h>

#define N_ROWS 1024
#define M_ROWS 1024
#define DD 256
#define QS 268   // shared-row stride (floats) for score tiles: 16B-aligned, bank-spread

__device__ float g_q[N_ROWS * DD];
__device__ float g_k[M_ROWS * DD];
__device__ float g_s[N_ROWS * M_ROWS];
__device__ float g_ctx[N_ROWS * DD];

__device__ __forceinline__ float tanh_fast(float x) {
    float y;
    asm("tanh.approx.f32 %0, %1;" : "=f"(y) : "f"(x));
    return y;
}

// ---------------------------------------------------------------------------
// GEMM (NT): out[n,j] = bias[j] + sum_d A[n,d] * B[j,d]
// z=0: q = f_r @ W_w.T + W_b ; z=1: k = f_r_prime @ Wp_w.T + Wp_b
// grid (16, 4, 2), block 256. Tile 64x64, K-chunk 32, 4x4 register tile.
// ---------------------------------------------------------------------------
__global__ void gemm_qk_kernel(const float* __restrict__ fr,
                               const float* __restrict__ frp,
                               const float* __restrict__ Ww,
                               const float* __restrict__ Wb,
                               const float* __restrict__ Wpw,
                               const float* __restrict__ Wpb) {
    const int z = blockIdx.z;
    const float* __restrict__ A    = z ? frp : fr;
    const float* __restrict__ B    = z ? Wpw : Ww;
    const float* __restrict__ bias = z ? Wpb : Wb;
    float* out = z ? g_k : g_q;

    const int bn = blockIdx.x * 64;
    const int bj = blockIdx.y * 64;
    const int tid = threadIdx.x;
    const int tx = tid & 15, ty = tid >> 4;

    __shared__ float As[64][33];
    __shared__ float Bs[64][33];

    float acc[4][4];
#pragma unroll
    for (int i = 0; i < 4; i++)
#pragma unroll
        for (int j = 0; j < 4; j++) acc[i][j] = 0.f;

    for (int k0 = 0; k0 < DD; k0 += 32) {
#pragma unroll
        for (int it = 0; it < 2; it++) {
            int idx = tid + it * 256;          // 0..511
            int row = idx >> 3;                // 0..63
            int c4  = (idx & 7) * 4;           // 0..28
            float4 va = *(const float4*)&A[(bn + row) * DD + k0 + c4];
            As[row][c4 + 0] = va.x; As[row][c4 + 1] = va.y;
            As[row][c4 + 2] = va.z; As[row][c4 + 3] = va.w;
            float4 vb = *(const float4*)&B[(bj + row) * DD + k0 + c4];
            Bs[row][c4 + 0] = vb.x; Bs[row][c4 + 1] = vb.y;
            Bs[row][c4 + 2] = vb.z; Bs[row][c4 + 3] = vb.w;
        }
        __syncthreads();
#pragma unroll 8
        for (int kk = 0; kk < 32; kk++) {
            float a[4], b[4];
#pragma unroll
            for (int i = 0; i < 4; i++) a[i] = As[ty * 4 + i][kk];
#pragma unroll
            for (int j = 0; j < 4; j++) b[j] = Bs[tx * 4 + j][kk];
#pragma unroll
            for (int i = 0; i < 4; i++)
#pragma unroll
                for (int j = 0; j < 4; j++) acc[i][j] += a[i] * b[j];
        }
        __syncthreads();
    }

    float4 bv = *(const float4*)&bias[bj + tx * 4];
#pragma unroll
    for (int i = 0; i < 4; i++) {
        float4 o;
        o.x = acc[i][0] + bv.x;
        o.y = acc[i][1] + bv.y;
        o.z = acc[i][2] + bv.z;
        o.w = acc[i][3] + bv.w;
        *(float4*)&out[(bn + ty * 4 + i) * DD + bj + tx * 4] = o;
    }
}

// ---------------------------------------------------------------------------
// Scores: s[n,m] = sum_d w[d] * tanh(q[n,d] + k[m,d])
// (the scalar bias w_b cancels in the softmax and is skipped)
// grid (32 m-tiles, 16 n-tiles), block 256. Tile 64n x 32m; full D in SMEM.
// Per-thread 4x2 register tile. MUFU-bound by design.
// ---------------------------------------------------------------------------
__global__ void score_kernel(const float* __restrict__ ww) {
    extern __shared__ float smem[];
    float* qs = smem;             // 64 x QS
    float* ks = smem + 64 * QS;   // 32 x QS
    float* ws = smem + 96 * QS;   // 256

    const int tid = threadIdx.x;
    const int bm = blockIdx.x * 32;
    const int bn = blockIdx.y * 64;

#pragma unroll
    for (int it = 0; it < 16; it++) {          // 64*64 float4s
        int idx = tid + it * 256;
        int row = idx >> 6;
        int c4  = (idx & 63) * 4;
        *(float4*)&qs[row * QS + c4] = *(const float4*)&g_q[(bn + row) * DD + c4];
    }
#pragma unroll
    for (int it = 0; it < 8; it++) {           // 32*64 float4s
        int idx = tid + it * 256;
        int row = idx >> 6;
        int c4  = (idx & 63) * 4;
        *(float4*)&ks[row * QS + c4] = *(const float4*)&g_k[(bm + row) * DD + c4];
    }
    if (tid < 64) *(float4*)&ws[tid * 4] = *(const float4*)&ww[tid * 4];
    __syncthreads();

    const int tx = tid & 15, ty = tid >> 4;
    const float* qp = &qs[(ty * 4) * QS];
    const float* kp = &ks[(tx * 2) * QS];

    float acc[4][2];
#pragma unroll
    for (int i = 0; i < 4; i++) { acc[i][0] = 0.f; acc[i][1] = 0.f; }

#pragma unroll 4
    for (int d4 = 0; d4 < 64; d4++) {
        float4 wv = *(const float4*)&ws[d4 * 4];
        float4 qv[4], kv[2];
#pragma unroll
        for (int i = 0; i < 4; i++) qv[i] = *(const float4*)&qp[i * QS + d4 * 4];
#pragma unroll
        for (int j = 0; j < 2; j++) kv[j] = *(const float4*)&kp[j * QS + d4 * 4];
#pragma unroll
        for (int i = 0; i < 4; i++)
#pragma unroll
            for (int j = 0; j < 2; j++) {
                acc[i][j] += wv.x * tanh_fast(qv[i].x + kv[j].x);
                acc[i][j] += wv.y * tanh_fast(qv[i].y + kv[j].y);
                acc[i][j] += wv.z * tanh_fast(qv[i].z + kv[j].z);
                acc[i][j] += wv.w * tanh_fast(qv[i].w + kv[j].w);
            }
    }

#pragma unroll
    for (int i = 0; i < 4; i++) {
        int n = bn + ty * 4 + i;
        *(float2*)&g_s[n * M_ROWS + bm + tx * 2] = make_float2(acc[i][0], acc[i][1]);
    }
}

// ---------------------------------------------------------------------------
// Row softmax over m + context[n,:] = sum_m alpha[n,m] * f_r_prime[m,:]
// grid 128 blocks x 8 rows, block 256 (one thread per d).
// ---------------------------------------------------------------------------
__global__ void smax_ctx_kernel(const float* __restrict__ frp) {
    __shared__ float ss[8 * 1024];   // 32KB: scores, then alpha in place

    const int tid = threadIdx.x;
    const int base = blockIdx.x * 8;

#pragma unroll
    for (int it = 0; it < 8; it++) {
        int idx = tid + it * 256;
        int row = idx >> 8;
        int c4  = (idx & 255) * 4;
        *(float4*)&ss[row * 1024 + c4] = *(const float4*)&g_s[(base + row) * M_ROWS + c4];
    }
    __syncthreads();

    const int wid = tid >> 5, lane = tid & 31;
    {
        float* rp = &ss[wid * 1024];  // warp wid owns row wid
        float mx = -1e30f;
#pragma unroll 4
        for (int t = 0; t < 32; t++) mx = fmaxf(mx, rp[t * 32 + lane]);
#pragma unroll
        for (int o = 16; o; o >>= 1) mx = fmaxf(mx, __shfl_xor_sync(0xffffffffu, mx, o));
        float sum = 0.f;
#pragma unroll 4
        for (int t = 0; t < 32; t++) sum += __expf(rp[t * 32 + lane] - mx);
#pragma unroll
        for (int o = 16; o; o >>= 1) sum += __shfl_xor_sync(0xffffffffu, sum, o);
        float inv = 1.f / sum;
#pragma unroll 4
        for (int t = 0; t < 32; t++) {
            int m = t * 32 + lane;
            rp[m] = __expf(rp[m] - mx) * inv;
        }
    }
    __syncthreads();

    const int d = tid;  // 0..255
    float acc[8];
#pragma unroll
    for (int r = 0; r < 8; r++) acc[r] = 0.f;

#pragma unroll 4
    for (int m = 0; m < 1024; m++) {
        float f = frp[m * DD + d];
#pragma unroll
        for (int r = 0; r < 8; r++) acc[r] += ss[r * 1024 + m] * f;
    }
#pragma unroll
    for (int r = 0; r < 8; r++) g_ctx[(base + r) * DD + d] = acc[r];
}

// ---------------------------------------------------------------------------
// Stage-2: sp[n] = ctx[n]·wp_w ; alpha_p = softmax over n (wp_b cancels);
// pool[d] = sum_n alpha_p[n] * ctx[n,d].  One block, 1024 threads.
// ---------------------------------------------------------------------------
__global__ void final_kernel(const float* __restrict__ wpw, float* __restrict__ out) {
    __shared__ float sp[1024];
    __shared__ float red[32];
    __shared__ float pr[1024];

    const int tid = threadIdx.x, lane = tid & 31, wid = tid >> 5;

    // Phase A: dot products, warp-cooperative (coalesced over d)
    {
        float4 w0 = *(const float4*)&wpw[lane * 8];
        float4 w1 = *(const float4*)&wpw[lane * 8 + 4];
        for (int t = 0; t < 32; t++) {
            int n = wid * 32 + t;
            float4 v0 = *(const float4*)&g_ctx[n * DD + lane * 8];
            float4 v1 = *(const float4*)&g_ctx[n * DD + lane * 8 + 4];
            float p = v0.x * w0.x + v0.y * w0.y + v0.z * w0.z + v0.w * w0.w
                    + v1.x * w1.x + v1.y * w1.y + v1.z * w1.z + v1.w * w1.w;
#pragma unroll
            for (int o = 16; o; o >>= 1) p += __shfl_xor_sync(0xffffffffu, p, o);
            if (lane == 0) sp[n] = p;
        }
    }
    __syncthreads();

    // Phase B: softmax over n
    float v = sp[tid];
    float mx = v;
#pragma unroll
    for (int o = 16; o; o >>= 1) mx = fmaxf(mx, __shfl_xor_sync(0xffffffffu, mx, o));
    if (lane == 0) red[wid] = mx;
    __syncthreads();
    if (tid < 32) {
        float m2 = red[lane];
#pragma unroll
        for (int o = 16; o; o >>= 1) m2 = fmaxf(m2, __shfl_xor_sync(0xffffffffu, m2, o));
        if (lane == 0) red[0] = m2;
    }
    __syncthreads();
    float gmx = red[0];
    __syncthreads();

    float e = __expf(v - gmx);
    float s = e;
#pragma unroll
    for (int o = 16; o; o >>= 1) s += __shfl_xor_sync(0xffffffffu, s, o);
    if (lane == 0) red[wid] = s;
    __syncthreads();
    if (tid < 32) {
        float s2 = red[lane];
#pragma unroll
        for (int o = 16; o; o >>= 1) s2 += __shfl_xor_sync(0xffffffffu, s2, o);
        if (lane == 0) red[0] = s2;
    }
    __syncthreads();
    float total = red[0];
    sp[tid] = e / total;
    __syncthreads();

    // Phase C: weighted pool over n (4-way split of n range)
    const int qq = tid >> 8, d = tid & 255;
    float acc = 0.f;
#pragma unroll 4
    for (int t = 0; t < 256; t++) {
        int n = qq * 256 + t;
        acc += sp[n] * g_ctx[n * DD + d];
    }
    pr[tid] = acc;
    __syncthreads();
    if (tid < 256)
        out[tid] = pr[tid] + pr[256 + tid] + pr[512 + tid] + pr[768 + tid];
}

// ---------------------------------------------------------------------------
extern "C" void kernel_launch(void* const* d_in, const int* in_sizes, int n_in,
                              void* d_out, int out_size) {
    const float* fr  = (const float*)d_in[0];
    const float* frp = (const float*)d_in[1];
    const float* Ww  = (const float*)d_in[2];
    const float* Wb  = (const float*)d_in[3];
    const float* Wpw = (const float*)d_in[4];
    const float* Wpb = (const float*)d_in[5];
    const float* ww  = (const float*)d_in[6];
    // d_in[7] = w_b, d_in[9] = wp_b: scalar biases cancel inside softmax — unused.
    const float* wpw = (const float*)d_in[8];
    float* out = (float*)d_out;

    const int score_smem = (96 * QS + 256) * (int)sizeof(float);  // ~103.9KB
    cudaFuncSetAttribute(score_kernel,
                         cudaFuncAttributeMaxDynamicSharedMemorySize, score_smem);

    gemm_qk_kernel<<<dim3(16, 4, 2), 256>>>(fr, frp, Ww, Wb, Wpw, Wpb);
    score_kernel<<<dim3(32, 16), 256, score_smem>>>(ww);
    smax_ctx_kernel<<<128, 256>>>(frp);
    final_kernel<<<1, 1024>>>(wpw, out);
}

// round 2
// speedup vs baseline: 1.4212x; 1.4212x over previous
#include <cuda_runtime.h>
#include <math.h>

#define N_ROWS 1024
#define M_ROWS 1024
#define DD 256
#define QS 268   // shared-row stride (floats) for score tiles: 16B-aligned, bank-spread

__device__ float g_q[N_ROWS * DD];
__device__ float g_k[M_ROWS * DD];
__device__ float g_s[N_ROWS * M_ROWS];
__device__ float g_ctx[N_ROWS * DD];
__device__ float g_sp[N_ROWS];
__device__ float g_alpha[N_ROWS];
__device__ float g_part[32 * DD];

__device__ __forceinline__ float tanh_fast(float x) {
    float y;
    asm("tanh.approx.f32 %0, %1;" : "=f"(y) : "f"(x));
    return y;
}

// ---------------------------------------------------------------------------
// GEMM (NT): out[n,j] = bias[j] + sum_d A[n,d] * B[j,d]
// z=0: q = f_r @ W_w.T + W_b ; z=1: k = f_r_prime @ Wp_w.T + Wp_b
// ---------------------------------------------------------------------------
__global__ void gemm_qk_kernel(const float* __restrict__ fr,
                               const float* __restrict__ frp,
                               const float* __restrict__ Ww,
                               const float* __restrict__ Wb,
                               const float* __restrict__ Wpw,
                               const float* __restrict__ Wpb) {
    const int z = blockIdx.z;
    const float* __restrict__ A    = z ? frp : fr;
    const float* __restrict__ B    = z ? Wpw : Ww;
    const float* __restrict__ bias = z ? Wpb : Wb;
    float* out = z ? g_k : g_q;

    const int bn = blockIdx.x * 64;
    const int bj = blockIdx.y * 64;
    const int tid = threadIdx.x;
    const int tx = tid & 15, ty = tid >> 4;

    __shared__ float As[64][33];
    __shared__ float Bs[64][33];

    float acc[4][4];
#pragma unroll
    for (int i = 0; i < 4; i++)
#pragma unroll
        for (int j = 0; j < 4; j++) acc[i][j] = 0.f;

    for (int k0 = 0; k0 < DD; k0 += 32) {
#pragma unroll
        for (int it = 0; it < 2; it++) {
            int idx = tid + it * 256;          // 0..511
            int row = idx >> 3;                // 0..63
            int c4  = (idx & 7) * 4;           // 0..28
            float4 va = *(const float4*)&A[(bn + row) * DD + k0 + c4];
            As[row][c4 + 0] = va.x; As[row][c4 + 1] = va.y;
            As[row][c4 + 2] = va.z; As[row][c4 + 3] = va.w;
            float4 vb = *(const float4*)&B[(bj + row) * DD + k0 + c4];
            Bs[row][c4 + 0] = vb.x; Bs[row][c4 + 1] = vb.y;
            Bs[row][c4 + 2] = vb.z; Bs[row][c4 + 3] = vb.w;
        }
        __syncthreads();
#pragma unroll 8
        for (int kk = 0; kk < 32; kk++) {
            float a[4], b[4];
#pragma unroll
            for (int i = 0; i < 4; i++) a[i] = As[ty * 4 + i][kk];
#pragma unroll
            for (int j = 0; j < 4; j++) b[j] = Bs[tx * 4 + j][kk];
#pragma unroll
            for (int i = 0; i < 4; i++)
#pragma unroll
                for (int j = 0; j < 4; j++) acc[i][j] += a[i] * b[j];
        }
        __syncthreads();
    }

    float4 bv = *(const float4*)&bias[bj + tx * 4];
#pragma unroll
    for (int i = 0; i < 4; i++) {
        float4 o;
        o.x = acc[i][0] + bv.x;
        o.y = acc[i][1] + bv.y;
        o.z = acc[i][2] + bv.z;
        o.w = acc[i][3] + bv.w;
        *(float4*)&out[(bn + ty * 4 + i) * DD + bj + tx * 4] = o;
    }
}

// ---------------------------------------------------------------------------
// Scores: s[n,m] = sum_d w[d] * tanh(q[n,d] + k[m,d])   (w_b cancels in softmax)
// grid (32 m-tiles, 16 n-tiles), block 256. Tile 64n x 32m; full D in SMEM.
// MUFU-bound by design (268M tanh ~ chip floor).
// ---------------------------------------------------------------------------
__global__ void score_kernel(const float* __restrict__ ww) {
    extern __shared__ float smem[];
    float* qs = smem;             // 64 x QS
    float* ks = smem + 64 * QS;   // 32 x QS
    float* ws = smem + 96 * QS;   // 256

    const int tid = threadIdx.x;
    const int bm = blockIdx.x * 32;
    const int bn = blockIdx.y * 64;

#pragma unroll
    for (int it = 0; it < 16; it++) {          // 64*64 float4s
        int idx = tid + it * 256;
        int row = idx >> 6;
        int c4  = (idx & 63) * 4;
        *(float4*)&qs[row * QS + c4] = *(const float4*)&g_q[(bn + row) * DD + c4];
    }
#pragma unroll
    for (int it = 0; it < 8; it++) {           // 32*64 float4s
        int idx = tid + it * 256;
        int row = idx >> 6;
        int c4  = (idx & 63) * 4;
        *(float4*)&ks[row * QS + c4] = *(const float4*)&g_k[(bm + row) * DD + c4];
    }
    if (tid < 64) *(float4*)&ws[tid * 4] = *(const float4*)&ww[tid * 4];
    __syncthreads();

    const int tx = tid & 15, ty = tid >> 4;
    const float* qp = &qs[(ty * 4) * QS];
    const float* kp = &ks[(tx * 2) * QS];

    float acc[4][2];
#pragma unroll
    for (int i = 0; i < 4; i++) { acc[i][0] = 0.f; acc[i][1] = 0.f; }

#pragma unroll 4
    for (int d4 = 0; d4 < 64; d4++) {
        float4 wv = *(const float4*)&ws[d4 * 4];
        float4 qv[4], kv[2];
#pragma unroll
        for (int i = 0; i < 4; i++) qv[i] = *(const float4*)&qp[i * QS + d4 * 4];
#pragma unroll
        for (int j = 0; j < 2; j++) kv[j] = *(const float4*)&kp[j * QS + d4 * 4];
#pragma unroll
        for (int i = 0; i < 4; i++)
#pragma unroll
            for (int j = 0; j < 2; j++) {
                acc[i][j] += wv.x * tanh_fast(qv[i].x + kv[j].x);
                acc[i][j] += wv.y * tanh_fast(qv[i].y + kv[j].y);
                acc[i][j] += wv.z * tanh_fast(qv[i].z + kv[j].z);
                acc[i][j] += wv.w * tanh_fast(qv[i].w + kv[j].w);
            }
    }

#pragma unroll
    for (int i = 0; i < 4; i++) {
        int n = bn + ty * 4 + i;
        *(float2*)&g_s[n * M_ROWS + bm + tx * 2] = make_float2(acc[i][0], acc[i][1]);
    }
}

// ---------------------------------------------------------------------------
// Row softmax over m + ctx[n,:] = sum_m alpha[n,m]*frp[m,:] + sp[n]=ctx[n]·wp_w
// grid 128 blocks x 8 rows, block 256.
// Context phase: per-thread 8r x 4d register tile, 4-way m-partition.
// ---------------------------------------------------------------------------
__global__ void smax_ctx_kernel(const float* __restrict__ frp,
                                const float* __restrict__ wpw) {
    __shared__ float ss[8 * 1024];   // scores -> alpha -> partials (reused)
    __shared__ float red[64];

    const int tid = threadIdx.x;
    const int base = blockIdx.x * 8;
    const int wid = tid >> 5, lane = tid & 31;

#pragma unroll
    for (int it = 0; it < 8; it++) {
        int idx = tid + it * 256;
        int row = idx >> 8;
        int c4  = (idx & 255) * 4;
        *(float4*)&ss[row * 1024 + c4] = *(const float4*)&g_s[(base + row) * M_ROWS + c4];
    }
    __syncthreads();

    // Softmax: warp wid owns row wid. Single exp pass (store e, then scale).
    {
        float* rp = &ss[wid * 1024];
        float mx = -1e30f;
#pragma unroll 8
        for (int t = 0; t < 32; t++) mx = fmaxf(mx, rp[t * 32 + lane]);
#pragma unroll
        for (int o = 16; o; o >>= 1) mx = fmaxf(mx, __shfl_xor_sync(0xffffffffu, mx, o));
        float sum = 0.f;
#pragma unroll 8
        for (int t = 0; t < 32; t++) {
            int m = t * 32 + lane;
            float e = __expf(rp[m] - mx);
            rp[m] = e;
            sum += e;
        }
#pragma unroll
        for (int o = 16; o; o >>= 1) sum += __shfl_xor_sync(0xffffffffu, sum, o);
        float inv = 1.f / sum;
#pragma unroll 8
        for (int t = 0; t < 32; t++) rp[t * 32 + lane] *= inv;
    }
    __syncthreads();

    // Context: partition p = tid>>6 handles m in [p*256, p*256+256); d = dg*4..+3
    const int p = tid >> 6, dg = tid & 63;
    const int d0 = dg * 4;
    float acc[8][4];
#pragma unroll
    for (int r = 0; r < 8; r++)
#pragma unroll
        for (int j = 0; j < 4; j++) acc[r][j] = 0.f;

    const int m0 = p * 256;
#pragma unroll 4
    for (int mi = 0; mi < 256; mi++) {
        int m = m0 + mi;
        float4 f = *(const float4*)&frp[m * DD + d0];
#pragma unroll
        for (int r = 0; r < 8; r++) {
            float a = ss[r * 1024 + m];   // broadcast LDS
            acc[r][0] += a * f.x;
            acc[r][1] += a * f.y;
            acc[r][2] += a * f.z;
            acc[r][3] += a * f.w;
        }
    }
    __syncthreads();

    // Partials into reused smem: layout [p][r][256 d]
#pragma unroll
    for (int r = 0; r < 8; r++)
        *(float4*)&ss[p * 2048 + r * 256 + d0] = *(float4*)acc[r];
    __syncthreads();

    // Final: thread tid owns d = tid; reduce 4 partitions, write ctx + sp contrib
    const int d = tid;
    const float wv = wpw[d];
    float vals[8];
#pragma unroll
    for (int r = 0; r < 8; r++) {
        float v = ss[0 * 2048 + r * 256 + d] + ss[1 * 2048 + r * 256 + d]
                + ss[2 * 2048 + r * 256 + d] + ss[3 * 2048 + r * 256 + d];
        g_ctx[(base + r) * DD + d] = v;
        vals[r] = v * wv;
    }
    __syncthreads();

    // Block-reduce vals[r] over 256 threads -> sp[base+r]
#pragma unroll
    for (int r = 0; r < 8; r++) {
        float v = vals[r];
#pragma unroll
        for (int o = 16; o; o >>= 1) v += __shfl_xor_sync(0xffffffffu, v, o);
        if (lane == 0) red[r * 8 + wid] = v;
    }
    __syncthreads();
    if (tid < 8) {
        float s = 0.f;
#pragma unroll
        for (int i = 0; i < 8; i++) s += red[tid * 8 + i];
        g_sp[base + tid] = s;
    }
}

// ---------------------------------------------------------------------------
// Stage-2 softmax over n (wp_b cancels). 1 block, 1024 threads.
// ---------------------------------------------------------------------------
__global__ void smax_n_kernel() {
    __shared__ float red[32];
    const int tid = threadIdx.x, lane = tid & 31, wid = tid >> 5;

    float v = g_sp[tid];
    float mx = v;
#pragma unroll
    for (int o = 16; o; o >>= 1) mx = fmaxf(mx, __shfl_xor_sync(0xffffffffu, mx, o));
    if (lane == 0) red[wid] = mx;
    __syncthreads();
    if (tid < 32) {
        float m2 = red[lane];
#pragma unroll
        for (int o = 16; o; o >>= 1) m2 = fmaxf(m2, __shfl_xor_sync(0xffffffffu, m2, o));
        if (lane == 0) red[0] = m2;
    }
    __syncthreads();
    float gmx = red[0];
    __syncthreads();

    float e = __expf(v - gmx);
    float s = e;
#pragma unroll
    for (int o = 16; o; o >>= 1) s += __shfl_xor_sync(0xffffffffu, s, o);
    if (lane == 0) red[wid] = s;
    __syncthreads();
    if (tid < 32) {
        float s2 = red[lane];
#pragma unroll
        for (int o = 16; o; o >>= 1) s2 += __shfl_xor_sync(0xffffffffu, s2, o);
        if (lane == 0) red[0] = s2;
    }
    __syncthreads();
    g_alpha[tid] = e / red[0];
}

// ---------------------------------------------------------------------------
// Partial pool: block b sums n in [32b, 32b+32). grid 32, block 256.
// ---------------------------------------------------------------------------
__global__ void pool_partial_kernel() {
    const int d = threadIdx.x;
    const int nb = blockIdx.x * 32;
    float acc = 0.f;
#pragma unroll 8
    for (int t = 0; t < 32; t++) {
        int n = nb + t;
        acc += g_alpha[n] * g_ctx[n * DD + d];
    }
    g_part[blockIdx.x * DD + d] = acc;
}

// Reduce 32 partials. 1 block, 256 threads.
__global__ void pool_reduce_kernel(float* __restrict__ out) {
    const int d = threadIdx.x;
    float acc = 0.f;
#pragma unroll
    for (int b = 0; b < 32; b++) acc += g_part[b * DD + d];
    out[d] = acc;
}

// ---------------------------------------------------------------------------
extern "C" void kernel_launch(void* const* d_in, const int* in_sizes, int n_in,
                              void* d_out, int out_size) {
    const float* fr  = (const float*)d_in[0];
    const float* frp = (const float*)d_in[1];
    const float* Ww  = (const float*)d_in[2];
    const float* Wb  = (const float*)d_in[3];
    const float* Wpw = (const float*)d_in[4];
    const float* Wpb = (const float*)d_in[5];
    const float* ww  = (const float*)d_in[6];
    // d_in[7] = w_b, d_in[9] = wp_b: scalar biases cancel inside softmax — unused.
    const float* wpw = (const float*)d_in[8];
    float* out = (float*)d_out;

    const int score_smem = (96 * QS + 256) * (int)sizeof(float);  // ~103.9KB
    cudaFuncSetAttribute(score_kernel,
                         cudaFuncAttributeMaxDynamicSharedMemorySize, score_smem);

    gemm_qk_kernel<<<dim3(16, 4, 2), 256>>>(fr, frp, Ww, Wb, Wpw, Wpb);
    score_kernel<<<dim3(32, 16), 256, score_smem>>>(ww);
    smax_ctx_kernel<<<128, 256>>>(frp, wpw);
    smax_n_kernel<<<1, 1024>>>();
    pool_partial_kernel<<<32, 256>>>();
    pool_reduce_kernel<<<1, 256>>>(out);
}